// round 12
// baseline (speedup 1.0000x reference)
#include <cuda_runtime.h>
#include <cuda.h>
#include <cstdint>
#include <cstddef>

// Problem dims
#define MDIM 8192
#define NDIM 4096
#define KDIM 4096
#define BLK  32

// GEMM tiling — 128x128 CTA tile, 2 CTAs/SM for cross-CTA overlap
#define TM 128
#define TN 128
#define KT 32                 // fp32 elements per K-chunk = one K-block = 128B row
#define NSTAGES 3
#define NKITER (KDIM / KT)    // 128
#define NWC 8                 // compute warps (2m x 4n, warp tile 64x32)
#define THREADS 288           // 8 compute warps + 1 producer warp
#define NTILES_N (NDIM / TN)  // 32

#define A_BYTES (TM * KT * 4)         // 16384
#define B_BYTES (TN * KT * 4)         // 16384
#define BBLK_BYTES (32 * KT * 4)      // 4096 per n-block
#define STAGE_BYTES (A_BYTES + B_BYTES)               // 32768
#define SMEM_DATA0 1024
#define SMEM_TOTAL (SMEM_DATA0 + NSTAGES * STAGE_BYTES)  // 99328 -> 2 CTAs/SM

#define OFF_FULL(s)  (16 + (s) * 8)
#define OFF_EMPTY(s) (64 + (s) * 8)
#define OFF_LIVE     512              // 128 bytes: live mask per k-block

// Scratch (static device globals: allowed, no runtime alloc)
__device__ float g_wm[(size_t)NDIM * (size_t)KDIM];   // masked+tf32+permuted W
__device__ float g_xt[(size_t)MDIM * (size_t)KDIM];   // tf32+permuted x
__device__ unsigned char g_live[NTILES_N * NKITER];   // [32][128], 4-bit masks

// ---------------- device helpers ----------------

__device__ __forceinline__ uint32_t smem_u32(const void* p) {
  uint32_t r;
  asm("{ .reg .u64 t; cvta.to.shared.u64 t, %1; cvt.u32.u64 %0, t; }"
      : "=r"(r) : "l"(p));
  return r;
}
__device__ __forceinline__ void mbar_init(uint32_t a, uint32_t cnt) {
  asm volatile("mbarrier.init.shared::cta.b64 [%0], %1;"
               :: "r"(a), "r"(cnt) : "memory");
}
__device__ __forceinline__ void mbar_expect_tx(uint32_t a, uint32_t bytes) {
  asm volatile("mbarrier.arrive.expect_tx.shared::cta.b64 _, [%0], %1;"
               :: "r"(a), "r"(bytes) : "memory");
}
__device__ __forceinline__ void mbar_arrive(uint32_t a) {
  asm volatile("mbarrier.arrive.shared::cta.b64 _, [%0];"
               :: "r"(a) : "memory");
}
__device__ __forceinline__ void mbar_wait(uint32_t a, uint32_t parity) {
  asm volatile(
      "{\n\t.reg .pred P;\n\t"
      "WL%=:\n\t"
      "mbarrier.try_wait.parity.acquire.cta.shared::cta.b64 P, [%0], %1, 0x989680;\n\t"
      "@P bra WD%=;\n\t"
      "bra WL%=;\n\t"
      "WD%=:\n\t}"
      :: "r"(a), "r"(parity) : "memory");
}
__device__ __forceinline__ void tma_load_2d(uint32_t smem_dst, const void* map,
                                            int cx, int cy, uint32_t bar) {
  asm volatile(
      "cp.async.bulk.tensor.2d.shared::cta.global.tile.mbarrier::complete_tx::bytes "
      "[%0], [%1, {%2, %3}], [%4];"
      :: "r"(smem_dst), "l"(map), "r"(cx), "r"(cy), "r"(bar) : "memory");
}
__device__ __forceinline__ uint32_t f2tf32(float f) {
  uint32_t u;
  asm("cvt.rna.tf32.f32 %0, %1;" : "=r"(u) : "f"(f));
  return u;
}
__device__ __forceinline__ void lds64(uint32_t addr, uint32_t& x, uint32_t& y) {
  asm volatile("ld.shared.v2.u32 {%0, %1}, [%2];"
               : "=r"(x), "=r"(y) : "r"(addr));
}
__device__ __forceinline__ void mma_tf32(float* c, uint32_t a0, uint32_t a1,
                                         uint32_t a2, uint32_t a3,
                                         uint32_t b0, uint32_t b1) {
  asm volatile(
      "mma.sync.aligned.m16n8k8.row.col.f32.tf32.tf32.f32 "
      "{%0,%1,%2,%3}, {%4,%5,%6,%7}, {%8,%9}, {%0,%1,%2,%3};"
      : "+f"(c[0]), "+f"(c[1]), "+f"(c[2]), "+f"(c[3])
      : "r"(a0), "r"(a1), "r"(a2), "r"(a3), "r"(b0), "r"(b1));
}

// ---------------- column permutation (R4-verified, unchanged) ----------------
// off = (c4&1)*8 + ks*16 + (c4>>1)*64 + h*4 within each 128B k-block row.

__device__ __forceinline__ int perm_src_col(int p) {
  int h  = p & 1;
  int c4 = ((p >> 1) & 1) | (((p >> 4) & 1) << 1);
  int ks = (p >> 2) & 3;
  return ks * 8 + c4 + 4 * h;
}

// ---------------- pre-pass kernels ----------------

__global__ void __launch_bounds__(256)
premask_kernel(const float4* __restrict__ w, const int* __restrict__ bm,
               float* __restrict__ wm) {
  int t = blockIdx.x * 256 + threadIdx.x;     // [NDIM][KDIM/32]
  int o  = t >> 7;
  int kb = t & 127;
  if (bm[((o >> 5) << 7) + kb] == 0) return;  // dead blocks never TMA-loaded
  const float4* src = w + (size_t)t * 8;
  uint4* dst = reinterpret_cast<uint4*>(wm) + (size_t)t * 8;
  float v[32];
  #pragma unroll
  for (int q = 0; q < 8; q++) {
    float4 f = src[q];
    v[q * 4 + 0] = f.x; v[q * 4 + 1] = f.y; v[q * 4 + 2] = f.z; v[q * 4 + 3] = f.w;
  }
  uint32_t ov[32];
  #pragma unroll
  for (int p = 0; p < 32; p++) ov[p] = f2tf32(v[perm_src_col(p)]);
  #pragma unroll
  for (int q = 0; q < 8; q++)
    dst[q] = make_uint4(ov[q * 4], ov[q * 4 + 1], ov[q * 4 + 2], ov[q * 4 + 3]);
}

__global__ void __launch_bounds__(256)
cvtx_kernel(const float4* __restrict__ x, float* __restrict__ xt) {
  int t = blockIdx.x * 256 + threadIdx.x;
  const float4* src = x + (size_t)t * 8;
  uint4* dst = reinterpret_cast<uint4*>(xt) + (size_t)t * 8;
  float v[32];
  #pragma unroll
  for (int q = 0; q < 8; q++) {
    float4 f = src[q];
    v[q * 4 + 0] = f.x; v[q * 4 + 1] = f.y; v[q * 4 + 2] = f.z; v[q * 4 + 3] = f.w;
  }
  uint32_t ov[32];
  #pragma unroll
  for (int p = 0; p < 32; p++) ov[p] = f2tf32(v[perm_src_col(p)]);
  #pragma unroll
  for (int q = 0; q < 8; q++)
    dst[q] = make_uint4(ov[q * 4], ov[q * 4 + 1], ov[q * 4 + 2], ov[q * 4 + 3]);
}

// Live mask for TN=128 tiles: bit j (j<4) = block (cn*4+j, kb) nonzero.
__global__ void __launch_bounds__(256)
livemask_kernel(const int* __restrict__ bm, unsigned char* __restrict__ lv) {
  int t = blockIdx.x * 256 + threadIdx.x;   // 0..4095
  int cn = t >> 7, kb = t & 127;
  unsigned b = 0;
  #pragma unroll
  for (int j = 0; j < 4; j++)
    b |= (bm[(cn * 4 + j) * 128 + kb] ? 1u : 0u) << j;
  lv[t] = (unsigned char)b;
}

// ---------------- GEMM ----------------
// CTA 128x128, 8 compute warps (2m x 4n, warp tile 64x32) + 1 producer.
// 3-stage TMA ring (97 KB smem) -> 2 CTAs/SM: each SMSP interleaves warps of
// two CTAs with independent sparsity masks and barrier phases, averaging the
// live-warp imbalance that gated R8 (dur*tensor% == 457us const across
// R8/R10: tensor-busy is at the rt=8 floor; idle is the only target).
//
// R11 crash root cause: producer flipped its empty-wait parity when the FILL
// cursor wrapped (end of kb=2), so the kb=3 wait used parity 1 = "second
// completion" while only one had occurred -> deadlock. Fix: independent wait
// cursor (wst, wph) advanced only when a wait executes.

__device__ __forceinline__ void lds_frag_a(uint32_t Ab, uint32_t cx,
                                           uint32_t* a) {
  #pragma unroll
  for (int mt = 0; mt < 4; mt++) {
    lds64(Ab + mt * 2048 + cx,        a[mt * 4 + 0], a[mt * 4 + 2]);
    lds64(Ab + mt * 2048 + 1024 + cx, a[mt * 4 + 1], a[mt * 4 + 3]);
  }
}
__device__ __forceinline__ void lds_frag_b(uint32_t Bb, uint32_t cx,
                                           uint32_t* b) {
  #pragma unroll
  for (int nt = 0; nt < 4; nt++)
    lds64(Bb + nt * 1024 + cx, b[nt * 2], b[nt * 2 + 1]);
}

__device__ __forceinline__ void stage_mma(uint32_t Ab, uint32_t Bb,
                                          const uint32_t* cxs,
                                          float acc[4][4][4]) {
  uint32_t a[2][16], b[2][8];
  lds_frag_b(Bb, cxs[0], b[0]);
  lds_frag_a(Ab, cxs[0], a[0]);
  #pragma unroll
  for (int ks = 0; ks < 4; ks++) {
    const int cur = ks & 1, nxt = cur ^ 1;
    if (ks < 3) {
      lds_frag_b(Bb, cxs[ks + 1], b[nxt]);
      lds_frag_a(Ab, cxs[ks + 1], a[nxt]);
    }
    #pragma unroll
    for (int mt = 0; mt < 4; mt++)
      #pragma unroll
      for (int nt = 0; nt < 4; nt++)
        mma_tf32(acc[mt][nt], a[cur][mt * 4 + 0], a[cur][mt * 4 + 1],
                 a[cur][mt * 4 + 2], a[cur][mt * 4 + 3],
                 b[cur][nt * 2], b[cur][nt * 2 + 1]);
  }
}

__global__ void __launch_bounds__(THREADS, 2)
bsl_gemm_kernel(const __grid_constant__ CUtensorMap tmA,
                const __grid_constant__ CUtensorMap tmB,
                const float* __restrict__ bias,
                float* __restrict__ out) {
  extern __shared__ char smem[];
  const uint32_t sb = smem_u32(smem);
  const int tid  = threadIdx.x;
  const int w    = tid >> 5;
  const int lane = tid & 31;
  const int grp  = lane >> 2;
  const int c4   = lane & 3;

  // grid: x = n-tile (32), y = m-tile (64)  -> wave-blocked for L2 reuse
  const int n0 = blockIdx.x * TN;
  const int m0 = blockIdx.y * TM;

  if (tid == 0) {
    #pragma unroll
    for (int s = 0; s < NSTAGES; s++) {
      mbar_init(sb + OFF_FULL(s), 1);
      mbar_init(sb + OFF_EMPTY(s), NWC);
    }
    asm volatile("fence.proxy.async.shared::cta;" ::: "memory");
  }
  if (tid < 32) {
    reinterpret_cast<uint32_t*>(smem + OFF_LIVE)[tid] =
        reinterpret_cast<const uint32_t*>(g_live)[blockIdx.x * 32 + tid];
  }
  __syncthreads();

  const unsigned char* lv = reinterpret_cast<const unsigned char*>(smem + OFF_LIVE);

  if (w == NWC) {
    // -------- producer warp --------
    if (lane == 0) {
      int st = 0;          // fill cursor
      int wst = 0, wph = 0; // wait cursor (advances only when a wait runs)
      for (int kb = 0; kb < NKITER; kb++) {
        if (kb >= NSTAGES) {
          mbar_wait(sb + OFF_EMPTY(wst), wph);
          if (++wst == NSTAGES) { wst = 0; wph ^= 1; }
        }
        const unsigned L = lv[kb];
        const uint32_t tx = (L ? A_BYTES : 0u) + (uint32_t)__popc(L) * BBLK_BYTES;
        mbar_expect_tx(sb + OFF_FULL(st), tx);
        const uint32_t dst = sb + SMEM_DATA0 + st * STAGE_BYTES;
        if (L) tma_load_2d(dst, &tmA, kb * KT, m0, sb + OFF_FULL(st));
        #pragma unroll
        for (int j = 0; j < 4; j++)
          if ((L >> j) & 1)
            tma_load_2d(dst + A_BYTES + j * BBLK_BYTES, &tmB, kb * KT,
                        n0 + j * 32, sb + OFF_FULL(st));
        if (++st == NSTAGES) st = 0;
      }
    }
    return;
  }

  // -------- compute warps: j0 = w>>1, m-half = w&1 (SMSP-distinct blocks) --
  const int j0  = w >> 1;            // the warp's n-block (0..3)
  const int wm_ = (w & 1) * 64;      // warp m offset (0 or 64)
  const int wn_ = j0 * 32;           // warp n offset

  const uint32_t arow0 = (uint32_t)((wm_ + grp) * 128);
  const uint32_t brow0 = (uint32_t)(j0 * BBLK_BYTES + grp * 128);
  const uint32_t xorb =
      (((uint32_t)(c4 & 1) << 3) | ((uint32_t)(c4 >> 1) << 6)) ^
      ((uint32_t)grp << 4);
  uint32_t cxs[4];
  #pragma unroll
  for (int ks = 0; ks < 4; ks++) cxs[ks] = ((uint32_t)(ks << 4)) ^ xorb;

  float acc[4][4][4];
  #pragma unroll
  for (int mt = 0; mt < 4; mt++)
    #pragma unroll
    for (int nt = 0; nt < 4; nt++)
      #pragma unroll
      for (int r = 0; r < 4; r++) acc[mt][nt][r] = 0.f;

  {
    int st = 0, ph = 0;
    for (int kb = 0; kb < NKITER; kb++) {
      mbar_wait(sb + OFF_FULL(st), ph);
      if ((lv[kb] >> j0) & 1) {
        const uint32_t base = sb + SMEM_DATA0 + st * STAGE_BYTES;
        stage_mma(base + arow0, base + A_BYTES + brow0, cxs, acc);
      }
      if (lane == 0) mbar_arrive(sb + OFF_EMPTY(st));
      if (++st == NSTAGES) { st = 0; ph ^= 1; }
    }
  }

  // -------- epilogue --------
  #pragma unroll
  for (int nt = 0; nt < 4; nt++) {
    const int col = n0 + wn_ + nt * 8 + c4 * 2;
    const float2 bv = *reinterpret_cast<const float2*>(bias + col);
    #pragma unroll
    for (int mt = 0; mt < 4; mt++) {
      const int row = m0 + wm_ + mt * 16 + grp;
      float2 o0, o1;
      o0.x = acc[mt][nt][0] + bv.x;
      o0.y = acc[mt][nt][1] + bv.y;
      o1.x = acc[mt][nt][2] + bv.x;
      o1.y = acc[mt][nt][3] + bv.y;
      *reinterpret_cast<float2*>(out + (size_t)row * NDIM + col) = o0;
      *reinterpret_cast<float2*>(out + (size_t)(row + 8) * NDIM + col) = o1;
    }
  }
}

// ---------------- host launch ----------------

typedef CUresult (*EncodeTiledFn)(
    CUtensorMap*, CUtensorMapDataType, cuuint32_t, void*, const cuuint64_t*,
    const cuuint64_t*, const cuuint32_t*, const cuuint32_t*,
    CUtensorMapInterleave, CUtensorMapSwizzle, CUtensorMapL2promotion,
    CUtensorMapFloatOOBfill);

extern "C" void kernel_launch(void* const* d_in, const int* in_sizes, int n_in,
                              void* d_out, int out_size) {
  const float* x = nullptr;
  const float* wgt = nullptr;
  const float* bias = nullptr;
  const int* bm = nullptr;
  for (int i = 0; i < n_in; i++) {
    long long sz = in_sizes[i];
    if (sz == (long long)MDIM * KDIM)       x    = (const float*)d_in[i];
    else if (sz == (long long)NDIM * KDIM)  wgt  = (const float*)d_in[i];
    else if (sz == NDIM)                    bias = (const float*)d_in[i];
    else if (sz == (NDIM / BLK) * (KDIM / BLK)) bm = (const int*)d_in[i];
  }

  void* wm_ptr = nullptr;
  void* xt_ptr = nullptr;
  void* lv_ptr = nullptr;
  cudaGetSymbolAddress(&wm_ptr, g_wm);
  cudaGetSymbolAddress(&xt_ptr, g_xt);
  cudaGetSymbolAddress(&lv_ptr, g_live);

  // 1) Pre-pass (one thread per 32-col k-block)
  premask_kernel<<<(NDIM * (KDIM / 32)) / 256, 256>>>(
      (const float4*)wgt, bm, (float*)wm_ptr);
  cvtx_kernel<<<(int)(((size_t)MDIM * (KDIM / 32)) / 256), 256>>>(
      (const float4*)x, (float*)xt_ptr);
  livemask_kernel<<<16, 256>>>(bm, (unsigned char*)lv_ptr);

  // 2) TMA descriptors
  EncodeTiledFn enc = nullptr;
  cudaDriverEntryPointQueryResult qr;
  cudaGetDriverEntryPoint("cuTensorMapEncodeTiled", (void**)&enc,
                          cudaEnableDefault, &qr);

  CUtensorMap tmA, tmB;
  {
    cuuint64_t dims[2]    = {(cuuint64_t)KDIM, (cuuint64_t)MDIM};
    cuuint64_t strides[1] = {(cuuint64_t)KDIM * sizeof(float)};
    cuuint32_t box[2]     = {KT, TM};
    cuuint32_t es[2]      = {1, 1};
    enc(&tmA, CU_TENSOR_MAP_DATA_TYPE_FLOAT32, 2, xt_ptr, dims, strides, box,
        es, CU_TENSOR_MAP_INTERLEAVE_NONE, CU_TENSOR_MAP_SWIZZLE_128B,
        CU_TENSOR_MAP_L2_PROMOTION_L2_128B, CU_TENSOR_MAP_FLOAT_OOB_FILL_NONE);
  }
  {
    cuuint64_t dims[2]    = {(cuuint64_t)KDIM, (cuuint64_t)NDIM};
    cuuint64_t strides[1] = {(cuuint64_t)KDIM * sizeof(float)};
    cuuint32_t box[2]     = {KT, 32};    // one 32x32 n-block per TMA
    cuuint32_t es[2]      = {1, 1};
    enc(&tmB, CU_TENSOR_MAP_DATA_TYPE_FLOAT32, 2, wm_ptr, dims, strides, box,
        es, CU_TENSOR_MAP_INTERLEAVE_NONE, CU_TENSOR_MAP_SWIZZLE_128B,
        CU_TENSOR_MAP_L2_PROMOTION_L2_128B, CU_TENSOR_MAP_FLOAT_OOB_FILL_NONE);
  }

  // 3) GEMM: grid.x = n-tiles (32), grid.y = m-tiles (64)
  cudaFuncSetAttribute(bsl_gemm_kernel,
                       cudaFuncAttributeMaxDynamicSharedMemorySize, SMEM_TOTAL);
  dim3 grid(NDIM / TN, MDIM / TM);
  bsl_gemm_kernel<<<grid, THREADS, SMEM_TOTAL>>>(tmA, tmB, bias, (float*)d_out);
}

// round 13
// speedup vs baseline: 1.0085x; 1.0085x over previous
#include <cuda_runtime.h>
#include <cuda.h>
#include <cstdint>
#include <cstddef>

// Problem dims
#define MDIM 8192
#define NDIM 4096
#define KDIM 4096
#define BLK  32

// GEMM tiling
#define TM 128
#define TN 256
#define KB 32                 // cols per k-block = one 128B SMEM row
#define NKB 128               // k-blocks total
#define KPS 2                 // k-blocks per pipeline stage
#define NSTAGES 2             // ring depth (drift window = 4 k-blocks, as R8)
#define NSTOT (NKB / KPS)     // 64 stages
#define NWC 16                // compute warps (2m x 8n, warp tile 64x32)
#define THREADS 544           // 16 compute warps + 1 producer warp

#define A_KB_BYTES (TM * KB * 4)      // 16384 per k-block
#define B_KB_BYTES (TN * KB * 4)      // 32768 per k-block
#define BBLK_BYTES (32 * KB * 4)      // 4096 per n-block
#define STAGE_BYTES (KPS * (A_KB_BYTES + B_KB_BYTES))   // 98304
#define SMEM_DATA0 1024
#define SMEM_TOTAL (SMEM_DATA0 + NSTAGES * STAGE_BYTES) // 197632 (= R8)

// stage-relative offsets: [A0 16K][A1 16K][B0 32K][B1 32K]
#define OFF_A(h) ((h) * A_KB_BYTES)
#define OFF_B(h) (KPS * A_KB_BYTES + (h) * B_KB_BYTES)

#define OFF_FULL(s)  (16 + (s) * 8)
#define OFF_EMPTY(s) (64 + (s) * 8)
#define OFF_LIVE     512              // 128 bytes: live mask per k-block

// Scratch (static device globals: allowed, no runtime alloc)
__device__ float g_wm[(size_t)NDIM * (size_t)KDIM];   // masked+tf32+permuted W
__device__ float g_xt[(size_t)MDIM * (size_t)KDIM];   // tf32+permuted x
__device__ unsigned char g_live[(NDIM / TN) * NKB];   // [16][128]

// ---------------- device helpers ----------------

__device__ __forceinline__ uint32_t smem_u32(const void* p) {
  uint32_t r;
  asm("{ .reg .u64 t; cvta.to.shared.u64 t, %1; cvt.u32.u64 %0, t; }"
      : "=r"(r) : "l"(p));
  return r;
}
__device__ __forceinline__ void mbar_init(uint32_t a, uint32_t cnt) {
  asm volatile("mbarrier.init.shared::cta.b64 [%0], %1;"
               :: "r"(a), "r"(cnt) : "memory");
}
__device__ __forceinline__ void mbar_expect_tx(uint32_t a, uint32_t bytes) {
  asm volatile("mbarrier.arrive.expect_tx.shared::cta.b64 _, [%0], %1;"
               :: "r"(a), "r"(bytes) : "memory");
}
__device__ __forceinline__ void mbar_arrive(uint32_t a) {
  asm volatile("mbarrier.arrive.shared::cta.b64 _, [%0];"
               :: "r"(a) : "memory");
}
__device__ __forceinline__ void mbar_wait(uint32_t a, uint32_t parity) {
  asm volatile(
      "{\n\t.reg .pred P;\n\t"
      "WL%=:\n\t"
      "mbarrier.try_wait.parity.acquire.cta.shared::cta.b64 P, [%0], %1, 0x989680;\n\t"
      "@P bra WD%=;\n\t"
      "bra WL%=;\n\t"
      "WD%=:\n\t}"
      :: "r"(a), "r"(parity) : "memory");
}
__device__ __forceinline__ void tma_load_2d(uint32_t smem_dst, const void* map,
                                            int cx, int cy, uint32_t bar) {
  asm volatile(
      "cp.async.bulk.tensor.2d.shared::cta.global.tile.mbarrier::complete_tx::bytes "
      "[%0], [%1, {%2, %3}], [%4];"
      :: "r"(smem_dst), "l"(map), "r"(cx), "r"(cy), "r"(bar) : "memory");
}
__device__ __forceinline__ uint32_t f2tf32(float f) {
  uint32_t u;
  asm("cvt.rna.tf32.f32 %0, %1;" : "=r"(u) : "f"(f));
  return u;
}
__device__ __forceinline__ void lds64(uint32_t addr, uint32_t& x, uint32_t& y) {
  asm volatile("ld.shared.v2.u32 {%0, %1}, [%2];"
               : "=r"(x), "=r"(y) : "r"(addr));
}
__device__ __forceinline__ void mma_tf32(float* c, uint32_t a0, uint32_t a1,
                                         uint32_t a2, uint32_t a3,
                                         uint32_t b0, uint32_t b1) {
  asm volatile(
      "mma.sync.aligned.m16n8k8.row.col.f32.tf32.tf32.f32 "
      "{%0,%1,%2,%3}, {%4,%5,%6,%7}, {%8,%9}, {%0,%1,%2,%3};"
      : "+f"(c[0]), "+f"(c[1]), "+f"(c[2]), "+f"(c[3])
      : "r"(a0), "r"(a1), "r"(a2), "r"(a3), "r"(b0), "r"(b1));
}

// ---------------- column permutation (R4-verified, unchanged) ----------------
// off = (c4&1)*8 + ks*16 + (c4>>1)*64 + h*4 within each 128B k-block row.
// Conflict-free LDS.64 under the SW128 XOR (grp<<4).

__device__ __forceinline__ int perm_src_col(int p) {
  int h  = p & 1;
  int c4 = ((p >> 1) & 1) | (((p >> 4) & 1) << 1);
  int ks = (p >> 2) & 3;
  return ks * 8 + c4 + 4 * h;
}

// ---------------- pre-pass kernels ----------------

__global__ void __launch_bounds__(256)
premask_kernel(const float4* __restrict__ w, const int* __restrict__ bm,
               float* __restrict__ wm) {
  int t = blockIdx.x * 256 + threadIdx.x;     // [NDIM][KDIM/32]
  int o  = t >> 7;
  int kb = t & 127;
  if (bm[((o >> 5) << 7) + kb] == 0) return;  // dead blocks never TMA-loaded
  const float4* src = w + (size_t)t * 8;
  uint4* dst = reinterpret_cast<uint4*>(wm) + (size_t)t * 8;
  float v[32];
  #pragma unroll
  for (int q = 0; q < 8; q++) {
    float4 f = src[q];
    v[q * 4 + 0] = f.x; v[q * 4 + 1] = f.y; v[q * 4 + 2] = f.z; v[q * 4 + 3] = f.w;
  }
  uint32_t ov[32];
  #pragma unroll
  for (int p = 0; p < 32; p++) ov[p] = f2tf32(v[perm_src_col(p)]);
  #pragma unroll
  for (int q = 0; q < 8; q++)
    dst[q] = make_uint4(ov[q * 4], ov[q * 4 + 1], ov[q * 4 + 2], ov[q * 4 + 3]);
}

__global__ void __launch_bounds__(256)
cvtx_kernel(const float4* __restrict__ x, float* __restrict__ xt) {
  int t = blockIdx.x * 256 + threadIdx.x;
  const float4* src = x + (size_t)t * 8;
  uint4* dst = reinterpret_cast<uint4*>(xt) + (size_t)t * 8;
  float v[32];
  #pragma unroll
  for (int q = 0; q < 8; q++) {
    float4 f = src[q];
    v[q * 4 + 0] = f.x; v[q * 4 + 1] = f.y; v[q * 4 + 2] = f.z; v[q * 4 + 3] = f.w;
  }
  uint32_t ov[32];
  #pragma unroll
  for (int p = 0; p < 32; p++) ov[p] = f2tf32(v[perm_src_col(p)]);
  #pragma unroll
  for (int q = 0; q < 8; q++)
    dst[q] = make_uint4(ov[q * 4], ov[q * 4 + 1], ov[q * 4 + 2], ov[q * 4 + 3]);
}

__global__ void __launch_bounds__(256)
livemask_kernel(const int* __restrict__ bm, unsigned char* __restrict__ lv) {
  int t = blockIdx.x * 256 + threadIdx.x;   // 0..2047
  int cn = t >> 7, kb = t & 127;
  unsigned b = 0;
  #pragma unroll
  for (int j = 0; j < 8; j++)
    b |= (bm[(cn * 8 + j) * 128 + kb] ? 1u : 0u) << j;
  lv[t] = (unsigned char)b;
}

// ---------------- GEMM ----------------
// CTA 128x256, 16 compute warps (2m x 8n, warp tile 64x32; j0=w>>1 so SMSP
// pairs host disjoint block sets — R8's proven map) + 1 producer.
// KPS=2: each pipeline stage carries TWO sequential k-blocks; NSTAGES=2 keeps
// the 4-k-block drift window and 192KB smem while HALVING barrier ops (64
// waits instead of 128) and averaging the per-SMSP live-load max over 2
// k-blocks. Sequential k order preserved (R9 lesson: reorder breaks the
// cross-CTA L2 contract on A). Parity derived from the loop counter only
// (R11 lesson: no mid-loop mutated wait cursors).

__device__ __forceinline__ void lds_frag_a(uint32_t Ab, uint32_t cx,
                                           uint32_t* a) {
  #pragma unroll
  for (int mt = 0; mt < 4; mt++) {
    lds64(Ab + mt * 2048 + cx,        a[mt * 4 + 0], a[mt * 4 + 2]);
    lds64(Ab + mt * 2048 + 1024 + cx, a[mt * 4 + 1], a[mt * 4 + 3]);
  }
}
__device__ __forceinline__ void lds_frag_b(uint32_t Bb, uint32_t cx,
                                           uint32_t* b) {
  #pragma unroll
  for (int nt = 0; nt < 4; nt++)
    lds64(Bb + nt * 1024 + cx, b[nt * 2], b[nt * 2 + 1]);
}

__device__ __forceinline__ void stage_mma(uint32_t Ab, uint32_t Bb,
                                          const uint32_t* cxs,
                                          float acc[4][4][4]) {
  uint32_t a[2][16], b[2][8];
  lds_frag_b(Bb, cxs[0], b[0]);
  lds_frag_a(Ab, cxs[0], a[0]);
  #pragma unroll
  for (int ks = 0; ks < 4; ks++) {
    const int cur = ks & 1, nxt = cur ^ 1;
    if (ks < 3) {
      lds_frag_b(Bb, cxs[ks + 1], b[nxt]);
      lds_frag_a(Ab, cxs[ks + 1], a[nxt]);
    }
    #pragma unroll
    for (int mt = 0; mt < 4; mt++)
      #pragma unroll
      for (int nt = 0; nt < 4; nt++)
        mma_tf32(acc[mt][nt], a[cur][mt * 4 + 0], a[cur][mt * 4 + 1],
                 a[cur][mt * 4 + 2], a[cur][mt * 4 + 3],
                 b[cur][nt * 2], b[cur][nt * 2 + 1]);
  }
}

__global__ void __launch_bounds__(THREADS, 1)
bsl_gemm_kernel(const __grid_constant__ CUtensorMap tmA,
                const __grid_constant__ CUtensorMap tmB,
                const float* __restrict__ bias,
                float* __restrict__ out) {
  extern __shared__ char smem[];
  const uint32_t sb = smem_u32(smem);
  const int tid  = threadIdx.x;
  const int w    = tid >> 5;
  const int lane = tid & 31;
  const int grp  = lane >> 2;
  const int c4   = lane & 3;

  // grid: x = n-tile (16), y = m-tile (64)  -> wave-blocked for L2 reuse
  const int n0 = blockIdx.x * TN;
  const int m0 = blockIdx.y * TM;

  if (tid == 0) {
    #pragma unroll
    for (int s = 0; s < NSTAGES; s++) {
      mbar_init(sb + OFF_FULL(s), 1);
      mbar_init(sb + OFF_EMPTY(s), NWC);
    }
    asm volatile("fence.proxy.async.shared::cta;" ::: "memory");
  }
  if (tid < 32) {
    reinterpret_cast<uint32_t*>(smem + OFF_LIVE)[tid] =
        reinterpret_cast<const uint32_t*>(g_live)[blockIdx.x * 32 + tid];
  }
  __syncthreads();

  const unsigned char* lv = reinterpret_cast<const unsigned char*>(smem + OFF_LIVE);

  if (w == NWC) {
    // -------- producer warp --------
    if (lane == 0) {
      for (int s = 0; s < NSTOT; s++) {
        const int st = s & 1;
        if (s >= NSTAGES) mbar_wait(sb + OFF_EMPTY(st), ((s - NSTAGES) >> 1) & 1);
        const unsigned L0 = lv[2 * s], L1 = lv[2 * s + 1];
        const uint32_t tx =
            (L0 ? A_KB_BYTES : 0u) + (uint32_t)__popc(L0) * BBLK_BYTES +
            (L1 ? A_KB_BYTES : 0u) + (uint32_t)__popc(L1) * BBLK_BYTES;
        mbar_expect_tx(sb + OFF_FULL(st), tx);
        const uint32_t dst = sb + SMEM_DATA0 + st * STAGE_BYTES;
        if (L0) tma_load_2d(dst + OFF_A(0), &tmA, (2 * s) * KB, m0,
                            sb + OFF_FULL(st));
        if (L1) tma_load_2d(dst + OFF_A(1), &tmA, (2 * s + 1) * KB, m0,
                            sb + OFF_FULL(st));
        #pragma unroll
        for (int j = 0; j < 8; j++) {
          if ((L0 >> j) & 1)
            tma_load_2d(dst + OFF_B(0) + j * BBLK_BYTES, &tmB, (2 * s) * KB,
                        n0 + j * 32, sb + OFF_FULL(st));
          if ((L1 >> j) & 1)
            tma_load_2d(dst + OFF_B(1) + j * BBLK_BYTES, &tmB, (2 * s + 1) * KB,
                        n0 + j * 32, sb + OFF_FULL(st));
        }
      }
    }
    return;
  }

  // -------- compute warps: j0 = w>>1 (SMSP-balanced, R8), m-half = w&1 --
  const int j0  = w >> 1;            // the warp's n-block (0..7)
  const int wm_ = (w & 1) * 64;      // warp m offset (0 or 64)
  const int wn_ = j0 * 32;           // warp n offset

  const uint32_t arow0 = (uint32_t)((wm_ + grp) * 128);
  const uint32_t brow0 = (uint32_t)(j0 * BBLK_BYTES + grp * 128);
  const uint32_t xorb =
      (((uint32_t)(c4 & 1) << 3) | ((uint32_t)(c4 >> 1) << 6)) ^
      ((uint32_t)grp << 4);
  uint32_t cxs[4];
  #pragma unroll
  for (int ks = 0; ks < 4; ks++) cxs[ks] = ((uint32_t)(ks << 4)) ^ xorb;

  float acc[4][4][4];
  #pragma unroll
  for (int mt = 0; mt < 4; mt++)
    #pragma unroll
    for (int nt = 0; nt < 4; nt++)
      #pragma unroll
      for (int r = 0; r < 4; r++) acc[mt][nt][r] = 0.f;

  for (int s = 0; s < NSTOT; s++) {
    const int st = s & 1;
    mbar_wait(sb + OFF_FULL(st), (s >> 1) & 1);
    const uint32_t base = sb + SMEM_DATA0 + st * STAGE_BYTES;
    if ((lv[2 * s] >> j0) & 1)
      stage_mma(base + OFF_A(0) + arow0, base + OFF_B(0) + brow0, cxs, acc);
    if ((lv[2 * s + 1] >> j0) & 1)
      stage_mma(base + OFF_A(1) + arow0, base + OFF_B(1) + brow0, cxs, acc);
    if (lane == 0) mbar_arrive(sb + OFF_EMPTY(st));
  }

  // -------- epilogue --------
  #pragma unroll
  for (int nt = 0; nt < 4; nt++) {
    const int col = n0 + wn_ + nt * 8 + c4 * 2;
    const float2 bv = *reinterpret_cast<const float2*>(bias + col);
    #pragma unroll
    for (int mt = 0; mt < 4; mt++) {
      const int row = m0 + wm_ + mt * 16 + grp;
      float2 o0, o1;
      o0.x = acc[mt][nt][0] + bv.x;
      o0.y = acc[mt][nt][1] + bv.y;
      o1.x = acc[mt][nt][2] + bv.x;
      o1.y = acc[mt][nt][3] + bv.y;
      *reinterpret_cast<float2*>(out + (size_t)row * NDIM + col) = o0;
      *reinterpret_cast<float2*>(out + (size_t)(row + 8) * NDIM + col) = o1;
    }
  }
}

// ---------------- host launch ----------------

typedef CUresult (*EncodeTiledFn)(
    CUtensorMap*, CUtensorMapDataType, cuuint32_t, void*, const cuuint64_t*,
    const cuuint64_t*, const cuuint32_t*, const cuuint32_t*,
    CUtensorMapInterleave, CUtensorMapSwizzle, CUtensorMapL2promotion,
    CUtensorMapFloatOOBfill);

extern "C" void kernel_launch(void* const* d_in, const int* in_sizes, int n_in,
                              void* d_out, int out_size) {
  const float* x = nullptr;
  const float* wgt = nullptr;
  const float* bias = nullptr;
  const int* bm = nullptr;
  for (int i = 0; i < n_in; i++) {
    long long sz = in_sizes[i];
    if (sz == (long long)MDIM * KDIM)       x    = (const float*)d_in[i];
    else if (sz == (long long)NDIM * KDIM)  wgt  = (const float*)d_in[i];
    else if (sz == NDIM)                    bias = (const float*)d_in[i];
    else if (sz == (NDIM / BLK) * (KDIM / BLK)) bm = (const int*)d_in[i];
  }

  void* wm_ptr = nullptr;
  void* xt_ptr = nullptr;
  void* lv_ptr = nullptr;
  cudaGetSymbolAddress(&wm_ptr, g_wm);
  cudaGetSymbolAddress(&xt_ptr, g_xt);
  cudaGetSymbolAddress(&lv_ptr, g_live);

  // 1) Pre-pass (one thread per 32-col k-block)
  premask_kernel<<<(NDIM * (KDIM / 32)) / 256, 256>>>(
      (const float4*)wgt, bm, (float*)wm_ptr);
  cvtx_kernel<<<(int)(((size_t)MDIM * (KDIM / 32)) / 256), 256>>>(
      (const float4*)x, (float*)xt_ptr);
  livemask_kernel<<<8, 256>>>(bm, (unsigned char*)lv_ptr);

  // 2) TMA descriptors
  EncodeTiledFn enc = nullptr;
  cudaDriverEntryPointQueryResult qr;
  cudaGetDriverEntryPoint("cuTensorMapEncodeTiled", (void**)&enc,
                          cudaEnableDefault, &qr);

  CUtensorMap tmA, tmB;
  {
    cuuint64_t dims[2]    = {(cuuint64_t)KDIM, (cuuint64_t)MDIM};
    cuuint64_t strides[1] = {(cuuint64_t)KDIM * sizeof(float)};
    cuuint32_t box[2]     = {KB, TM};
    cuuint32_t es[2]      = {1, 1};
    enc(&tmA, CU_TENSOR_MAP_DATA_TYPE_FLOAT32, 2, xt_ptr, dims, strides, box,
        es, CU_TENSOR_MAP_INTERLEAVE_NONE, CU_TENSOR_MAP_SWIZZLE_128B,
        CU_TENSOR_MAP_L2_PROMOTION_L2_128B, CU_TENSOR_MAP_FLOAT_OOB_FILL_NONE);
  }
  {
    cuuint64_t dims[2]    = {(cuuint64_t)KDIM, (cuuint64_t)NDIM};
    cuuint64_t strides[1] = {(cuuint64_t)KDIM * sizeof(float)};
    cuuint32_t box[2]     = {KB, 32};    // one 32x32 n-block per TMA
    cuuint32_t es[2]      = {1, 1};
    enc(&tmB, CU_TENSOR_MAP_DATA_TYPE_FLOAT32, 2, wm_ptr, dims, strides, box,
        es, CU_TENSOR_MAP_INTERLEAVE_NONE, CU_TENSOR_MAP_SWIZZLE_128B,
        CU_TENSOR_MAP_L2_PROMOTION_L2_128B, CU_TENSOR_MAP_FLOAT_OOB_FILL_NONE);
  }

  // 3) GEMM: grid.x = n-tiles (16), grid.y = m-tiles (64)
  cudaFuncSetAttribute(bsl_gemm_kernel,
                       cudaFuncAttributeMaxDynamicSharedMemorySize, SMEM_TOTAL);
  dim3 grid(NDIM / TN, MDIM / TM);
  bsl_gemm_kernel<<<grid, THREADS, SMEM_TOTAL>>>(tmA, tmB, bias, (float*)d_out);
}